// round 10
// baseline (speedup 1.0000x reference)
#include <cuda_runtime.h>

#define DIM 128
#define NMAX 50000
#define EMAX 800000

// ---- static scratch (no allocation allowed) ----
__device__ __align__(16) float g_xw[(size_t)NMAX * DIM];   // x @ W
__device__ int   g_degi[NMAX];        // in-edge count (no self loop)
__device__ float g_dinv[NMAX];        // (deg+1)^-0.5
__device__ int   g_off[NMAX + 1];     // CSR offsets
__device__ int   g_cursor[NMAX];      // CSR fill cursors
__device__ int   g_csr_col[EMAX];     // CSR column (source of message)
__device__ float g_csr_w[EMAX];       // precomputed norm weight
__device__ float g_sum[DIM];
__device__ float g_sumsq[DIM];
__device__ float g_mean[DIM];
__device__ float g_istd[DIM];

// K1: zero degree counters + BN accumulators
__global__ void k_init(int N) {
    int i = blockIdx.x * blockDim.x + threadIdx.x;
    if (i < N) g_degi[i] = 0;
    if (i < DIM) { g_sum[i] = 0.0f; g_sumsq[i] = 0.0f; }
}

// K2: count in-edges per row (int32 edge indices!)
__global__ void k_degree(const int* __restrict__ row, int E) {
    int e = blockIdx.x * blockDim.x + threadIdx.x;
    if (e < E) atomicAdd(&g_degi[row[e]], 1);
}

// K3: dinv = (deg + 1)^-0.5  (+1 = self loop)
__global__ void k_dinv(int N) {
    int i = blockIdx.x * blockDim.x + threadIdx.x;
    if (i < N) g_dinv[i] = rsqrtf((float)(g_degi[i] + 1));
}

// K4: single-block exclusive scan of degrees -> CSR offsets; zero cursors
__global__ void k_scan(int N) {
    __shared__ int sh[1024];
    int t = threadIdx.x;
    int chunk = (N + 1023) / 1024;
    int lo = t * chunk;
    int hi = min(lo + chunk, N);
    int s = 0;
    for (int i = lo; i < hi; i++) s += g_degi[i];
    sh[t] = s;
    __syncthreads();
    // Hillis-Steele inclusive scan
    for (int off = 1; off < 1024; off <<= 1) {
        int v = (t >= off) ? sh[t - off] : 0;
        __syncthreads();
        sh[t] += v;
        __syncthreads();
    }
    int run = (t == 0) ? 0 : sh[t - 1];
    for (int i = lo; i < hi; i++) {
        g_off[i] = run;
        g_cursor[i] = 0;
        run += g_degi[i];
    }
    if (lo <= N && hi == N) g_off[N] = run;
}

// K5: fill CSR (col index + precomputed weight)
__global__ void k_fill(const int* __restrict__ row,
                       const int* __restrict__ col, int E) {
    int e = blockIdx.x * blockDim.x + threadIdx.x;
    if (e >= E) return;
    int r = row[e];
    int c = col[e];
    int pos = g_off[r] + atomicAdd(&g_cursor[r], 1);
    g_csr_col[pos] = c;
    g_csr_w[pos] = g_dinv[r] * g_dinv[c];
}

// K6: xw = x @ W.  128 threads (one per output column), 8 nodes per block.
#define NPB 8
__global__ void k_gemm(const float* __restrict__ x, const float* __restrict__ W, int N) {
    __shared__ float xs[NPB][DIM];
    int tid = threadIdx.x;
    int base = blockIdx.x * NPB;
#pragma unroll
    for (int m = 0; m < NPB; m++) {
        int n = base + m;
        xs[m][tid] = (n < N) ? x[(size_t)n * DIM + tid] : 0.0f;
    }
    __syncthreads();
    float acc[NPB];
#pragma unroll
    for (int m = 0; m < NPB; m++) acc[m] = 0.0f;
#pragma unroll 4
    for (int k = 0; k < DIM; k++) {
        float wv = W[k * DIM + tid];
#pragma unroll
        for (int m = 0; m < NPB; m++) acc[m] = fmaf(xs[m][k], wv, acc[m]);
    }
#pragma unroll
    for (int m = 0; m < NPB; m++) {
        int n = base + m;
        if (n < N) g_xw[(size_t)n * DIM + tid] = acc[m];
    }
}

// K7: gather-aggregate. One warp per node, lane owns one float4 (32*4 = 128).
// out[r] = sum_{e in CSR[r]} xw[col_e]*w_e  +  xw[r]*dinv[r]^2  +  b
__global__ void k_aggregate(float* __restrict__ out, const float* __restrict__ b, int N) {
    int warp = (blockIdx.x * blockDim.x + threadIdx.x) >> 5;
    int lane = threadIdx.x & 31;
    if (warp >= N) return;
    int r = warp;
    const float4* xw4 = reinterpret_cast<const float4*>(g_xw);

    float di = g_dinv[r];
    float s = di * di;
    float4 acc = xw4[(size_t)r * 32 + lane];   // self loop
    acc.x *= s; acc.y *= s; acc.z *= s; acc.w *= s;

    int k0 = g_off[r], k1 = g_off[r + 1];
    int k = k0;
    for (; k + 1 < k1; k += 2) {
        int c0 = g_csr_col[k];     float w0 = g_csr_w[k];
        int c1 = g_csr_col[k + 1]; float w1 = g_csr_w[k + 1];
        float4 v0 = xw4[(size_t)c0 * 32 + lane];
        float4 v1 = xw4[(size_t)c1 * 32 + lane];
        acc.x = fmaf(v0.x, w0, acc.x); acc.y = fmaf(v0.y, w0, acc.y);
        acc.z = fmaf(v0.z, w0, acc.z); acc.w = fmaf(v0.w, w0, acc.w);
        acc.x = fmaf(v1.x, w1, acc.x); acc.y = fmaf(v1.y, w1, acc.y);
        acc.z = fmaf(v1.z, w1, acc.z); acc.w = fmaf(v1.w, w1, acc.w);
    }
    if (k < k1) {
        int c = g_csr_col[k]; float w = g_csr_w[k];
        float4 v = xw4[(size_t)c * 32 + lane];
        acc.x = fmaf(v.x, w, acc.x); acc.y = fmaf(v.y, w, acc.y);
        acc.z = fmaf(v.z, w, acc.z); acc.w = fmaf(v.w, w, acc.w);
    }

    float4 bb = reinterpret_cast<const float4*>(b)[lane];
    acc.x += bb.x; acc.y += bb.y; acc.z += bb.z; acc.w += bb.w;
    reinterpret_cast<float4*>(out)[(size_t)r * 32 + lane] = acc;
}

// K8: per-column sum / sumsq (block-local then one atomic per block per column)
__global__ void k_colstats(const float* __restrict__ out, int N) {
    int j = threadIdx.x;  // 0..127
    float s = 0.0f, s2 = 0.0f;
    for (int i = blockIdx.x; i < N; i += gridDim.x) {
        float v = out[(size_t)i * DIM + j];
        s += v;
        s2 += v * v;
    }
    atomicAdd(&g_sum[j], s);
    atomicAdd(&g_sumsq[j], s2);
}

// K9: finalize mean / inv-std
__global__ void k_finstats(int N) {
    int j = threadIdx.x;
    float invN = 1.0f / (float)N;
    float m = g_sum[j] * invN;
    float var = g_sumsq[j] * invN - m * m;
    g_mean[j] = m;
    g_istd[j] = rsqrtf(var + 1e-5f);
}

// K10: y = relu((out - mean) * istd * gamma + beta) + x, in place on d_out
__global__ void k_final(float* __restrict__ out, const float* __restrict__ x,
                        const float* __restrict__ gamma, const float* __restrict__ beta,
                        int nvec) {
    int idx = blockIdx.x * blockDim.x + threadIdx.x;  // float4 index
    if (idx >= nvec) return;
    int c = (idx & 31) * 4;
    float4 v = reinterpret_cast<float4*>(out)[idx];
    float4 xv = reinterpret_cast<const float4*>(x)[idx];
    float4 y;
    y.x = fmaxf((v.x - g_mean[c + 0]) * g_istd[c + 0] * gamma[c + 0] + beta[c + 0], 0.0f) + xv.x;
    y.y = fmaxf((v.y - g_mean[c + 1]) * g_istd[c + 1] * gamma[c + 1] + beta[c + 1], 0.0f) + xv.y;
    y.z = fmaxf((v.z - g_mean[c + 2]) * g_istd[c + 2] * gamma[c + 2] + beta[c + 2], 0.0f) + xv.z;
    y.w = fmaxf((v.w - g_mean[c + 3]) * g_istd[c + 3] * gamma[c + 3] + beta[c + 3], 0.0f) + xv.w;
    reinterpret_cast<float4*>(out)[idx] = y;
}

extern "C" void kernel_launch(void* const* d_in, const int* in_sizes, int n_in,
                              void* d_out, int out_size) {
    const float* x     = (const float*)d_in[0];
    const int*   ei    = (const int*)d_in[1];   // int32! (JAX default x64-disabled)
    const float* W     = (const float*)d_in[2];
    const float* b     = (const float*)d_in[3];
    const float* gamma = (const float*)d_in[4];
    const float* beta  = (const float*)d_in[5];
    float* out = (float*)d_out;

    int N = in_sizes[0] / DIM;         // 50000
    int E = in_sizes[1] / 2;           // 800000
    const int* row = ei;               // edge_index[0]
    const int* col = ei + E;           // edge_index[1]
    int nvec = N * (DIM / 4);

    k_init<<<(N + 255) / 256, 256>>>(N);
    k_degree<<<(E + 255) / 256, 256>>>(row, E);
    k_dinv<<<(N + 255) / 256, 256>>>(N);
    k_scan<<<1, 1024>>>(N);
    k_fill<<<(E + 255) / 256, 256>>>(row, col, E);
    k_gemm<<<(N + NPB - 1) / NPB, DIM>>>(x, W, N);
    k_aggregate<<<(N * 32 + 255) / 256, 256>>>(out, b, N);
    k_colstats<<<512, DIM>>>(out, N);
    k_finstats<<<1, DIM>>>(N);
    k_final<<<(nvec + 255) / 256, 256>>>(out, x, gamma, beta, nvec);
}

// round 11
// speedup vs baseline: 1.4202x; 1.4202x over previous
#include <cuda_runtime.h>

#define DIM 128
#define NMAX 50000
#define EMAX 800000
#define SCAN_CHUNK 1024                       // elements per scan block
#define SCAN_B ((NMAX + SCAN_CHUNK - 1) / SCAN_CHUNK)  // 49

// ---- static scratch (no allocation allowed) ----
__device__ __align__(16) float g_xw[(size_t)NMAX * DIM];   // x @ W
__device__ int   g_degi[NMAX];        // in-edge count (no self loop)
__device__ float g_dinv[NMAX];        // (deg+1)^-0.5
__device__ int   g_off[NMAX + 1];     // CSR offsets
__device__ int   g_cursor[NMAX];      // CSR fill cursors
__device__ int   g_csr_col[EMAX];     // CSR column (source of message)
__device__ float g_csr_w[EMAX];       // precomputed norm weight
__device__ int   g_bsum[SCAN_B];      // per-block sums
__device__ int   g_bbase[SCAN_B];     // per-block exclusive bases
__device__ float g_sum[DIM];
__device__ float g_sumsq[DIM];
__device__ float g_mean[DIM];
__device__ float g_istd[DIM];

// K1: zero degree counters + BN accumulators
__global__ void k_init(int N) {
    int i = blockIdx.x * blockDim.x + threadIdx.x;
    if (i < N) g_degi[i] = 0;
    if (i < DIM) { g_sum[i] = 0.0f; g_sumsq[i] = 0.0f; }
}

// K2: count in-edges per row (int32 edge indices)
__global__ void k_degree(const int* __restrict__ row, int E) {
    int e = blockIdx.x * blockDim.x + threadIdx.x;
    if (e < E) atomicAdd(&g_degi[row[e]], 1);
}

// K3: dinv = (deg + 1)^-0.5
__global__ void k_dinv(int N) {
    int i = blockIdx.x * blockDim.x + threadIdx.x;
    if (i < N) g_dinv[i] = rsqrtf((float)(g_degi[i] + 1));
}

// ---- device-wide scan, 3 phases ----

// S1: per-block sums (256 threads x 4 elements)
__global__ void k_scan_sum(int N) {
    __shared__ int wsum[8];
    int t = threadIdx.x;
    int base = blockIdx.x * SCAN_CHUNK + t * 4;
    int s = 0;
#pragma unroll
    for (int j = 0; j < 4; j++) {
        int i = base + j;
        if (i < N) s += g_degi[i];
    }
#pragma unroll
    for (int o = 16; o > 0; o >>= 1) s += __shfl_down_sync(0xffffffffu, s, o);
    if ((t & 31) == 0) wsum[t >> 5] = s;
    __syncthreads();
    if (t == 0) {
        int tot = 0;
#pragma unroll
        for (int w = 0; w < 8; w++) tot += wsum[w];
        g_bsum[blockIdx.x] = tot;
    }
}

// S2: exclusive scan of SCAN_B block sums (one small block)
__global__ void k_scan_top(int N) {
    __shared__ int sh[SCAN_B];
    int t = threadIdx.x;
    if (t < SCAN_B) sh[t] = g_bsum[t];
    __syncthreads();
    if (t == 0) {
        int run = 0;
        for (int i = 0; i < SCAN_B; i++) {
            g_bbase[i] = run;
            run += sh[i];
        }
        g_off[N] = run;   // total = E
    }
}

// S3: per-block exclusive scan + write offsets, zero cursors
__global__ void k_scan_write(int N) {
    __shared__ int wbase_sh[8];
    int t = threadIdx.x;
    int lane = t & 31, wid = t >> 5;
    int base = blockIdx.x * SCAN_CHUNK + t * 4;
    int v[4];
#pragma unroll
    for (int j = 0; j < 4; j++) {
        int i = base + j;
        v[j] = (i < N) ? g_degi[i] : 0;
    }
    int tsum = v[0] + v[1] + v[2] + v[3];
    // warp inclusive scan of tsum
    int inc = tsum;
#pragma unroll
    for (int o = 1; o < 32; o <<= 1) {
        int p = __shfl_up_sync(0xffffffffu, inc, o);
        if (lane >= o) inc += p;
    }
    if (lane == 31) wbase_sh[wid] = inc;
    __syncthreads();
    int wbase = 0;
    if (t < 8) {
        // tiny serial exclusive scan in warp 0's first 8 lanes via shared
    }
    __syncthreads();
    // compute warp base serially (cheap: 8 values)
    int wb = 0;
    for (int w = 0; w < wid; w++) wb += wbase_sh[w];
    wbase = wb;
    int texcl = wbase + inc - tsum;           // exclusive prefix of this thread
    int gbase = g_bbase[blockIdx.x];
    int run = gbase + texcl;
#pragma unroll
    for (int j = 0; j < 4; j++) {
        int i = base + j;
        if (i < N) {
            g_off[i] = run;
            g_cursor[i] = 0;
            run += v[j];
        }
    }
}

// K5: fill CSR (col index + precomputed weight)
__global__ void k_fill(const int* __restrict__ row,
                       const int* __restrict__ col, int E) {
    int e = blockIdx.x * blockDim.x + threadIdx.x;
    if (e >= E) return;
    int r = row[e];
    int c = col[e];
    int pos = g_off[r] + atomicAdd(&g_cursor[r], 1);
    g_csr_col[pos] = c;
    g_csr_w[pos] = g_dinv[r] * g_dinv[c];
}

// K6: xw = x @ W.  128 threads (one per output column), 8 nodes per block.
#define NPB 8
__global__ void k_gemm(const float* __restrict__ x, const float* __restrict__ W, int N) {
    __shared__ float xs[NPB][DIM];
    int tid = threadIdx.x;
    int base = blockIdx.x * NPB;
#pragma unroll
    for (int m = 0; m < NPB; m++) {
        int n = base + m;
        xs[m][tid] = (n < N) ? x[(size_t)n * DIM + tid] : 0.0f;
    }
    __syncthreads();
    float acc[NPB];
#pragma unroll
    for (int m = 0; m < NPB; m++) acc[m] = 0.0f;
#pragma unroll 4
    for (int k = 0; k < DIM; k++) {
        float wv = W[k * DIM + tid];
#pragma unroll
        for (int m = 0; m < NPB; m++) acc[m] = fmaf(xs[m][k], wv, acc[m]);
    }
#pragma unroll
    for (int m = 0; m < NPB; m++) {
        int n = base + m;
        if (n < N) g_xw[(size_t)n * DIM + tid] = acc[m];
    }
}

// K7: gather-aggregate + fused BN column stats.
// One warp per node, lane owns one float4. Block accumulates sum/sumsq in
// shared, then one global atomic per column per block.
__global__ void k_aggregate(float* __restrict__ out, const float* __restrict__ b, int N) {
    __shared__ float s_sum[DIM];
    __shared__ float s_sq[DIM];
    int t = threadIdx.x;
    if (t < DIM) { s_sum[t] = 0.0f; s_sq[t] = 0.0f; }
    __syncthreads();

    int warp = (blockIdx.x * blockDim.x + t) >> 5;
    int lane = t & 31;
    bool active = (warp < N);
    const float4* xw4 = reinterpret_cast<const float4*>(g_xw);

    float4 acc = make_float4(0.f, 0.f, 0.f, 0.f);
    if (active) {
        int r = warp;
        float di = g_dinv[r];
        float s = di * di;
        acc = xw4[(size_t)r * 32 + lane];   // self loop
        acc.x *= s; acc.y *= s; acc.z *= s; acc.w *= s;

        int k0 = g_off[r], k1 = g_off[r + 1];
        int k = k0;
        for (; k + 1 < k1; k += 2) {
            int c0 = g_csr_col[k];     float w0 = g_csr_w[k];
            int c1 = g_csr_col[k + 1]; float w1 = g_csr_w[k + 1];
            float4 v0 = xw4[(size_t)c0 * 32 + lane];
            float4 v1 = xw4[(size_t)c1 * 32 + lane];
            acc.x = fmaf(v0.x, w0, acc.x); acc.y = fmaf(v0.y, w0, acc.y);
            acc.z = fmaf(v0.z, w0, acc.z); acc.w = fmaf(v0.w, w0, acc.w);
            acc.x = fmaf(v1.x, w1, acc.x); acc.y = fmaf(v1.y, w1, acc.y);
            acc.z = fmaf(v1.z, w1, acc.z); acc.w = fmaf(v1.w, w1, acc.w);
        }
        if (k < k1) {
            int c = g_csr_col[k]; float w = g_csr_w[k];
            float4 v = xw4[(size_t)c * 32 + lane];
            acc.x = fmaf(v.x, w, acc.x); acc.y = fmaf(v.y, w, acc.y);
            acc.z = fmaf(v.z, w, acc.z); acc.w = fmaf(v.w, w, acc.w);
        }

        float4 bb = reinterpret_cast<const float4*>(b)[lane];
        acc.x += bb.x; acc.y += bb.y; acc.z += bb.z; acc.w += bb.w;
        reinterpret_cast<float4*>(out)[(size_t)warp * 32 + lane] = acc;

        int c0 = lane * 4;
        atomicAdd(&s_sum[c0 + 0], acc.x); atomicAdd(&s_sq[c0 + 0], acc.x * acc.x);
        atomicAdd(&s_sum[c0 + 1], acc.y); atomicAdd(&s_sq[c0 + 1], acc.y * acc.y);
        atomicAdd(&s_sum[c0 + 2], acc.z); atomicAdd(&s_sq[c0 + 2], acc.z * acc.z);
        atomicAdd(&s_sum[c0 + 3], acc.w); atomicAdd(&s_sq[c0 + 3], acc.w * acc.w);
    }
    __syncthreads();
    if (t < DIM) {
        atomicAdd(&g_sum[t], s_sum[t]);
        atomicAdd(&g_sumsq[t], s_sq[t]);
    }
}

// K8: finalize mean / inv-std
__global__ void k_finstats(int N) {
    int j = threadIdx.x;
    float invN = 1.0f / (float)N;
    float m = g_sum[j] * invN;
    float var = g_sumsq[j] * invN - m * m;
    g_mean[j] = m;
    g_istd[j] = rsqrtf(var + 1e-5f);
}

// K9: y = relu((out - mean) * istd * gamma + beta) + x, in place on d_out
__global__ void k_final(float* __restrict__ out, const float* __restrict__ x,
                        const float* __restrict__ gamma, const float* __restrict__ beta,
                        int nvec) {
    int idx = blockIdx.x * blockDim.x + threadIdx.x;  // float4 index
    if (idx >= nvec) return;
    int c = (idx & 31) * 4;
    float4 v = reinterpret_cast<float4*>(out)[idx];
    float4 xv = reinterpret_cast<const float4*>(x)[idx];
    float4 y;
    y.x = fmaxf((v.x - g_mean[c + 0]) * g_istd[c + 0] * gamma[c + 0] + beta[c + 0], 0.0f) + xv.x;
    y.y = fmaxf((v.y - g_mean[c + 1]) * g_istd[c + 1] * gamma[c + 1] + beta[c + 1], 0.0f) + xv.y;
    y.z = fmaxf((v.z - g_mean[c + 2]) * g_istd[c + 2] * gamma[c + 2] + beta[c + 2], 0.0f) + xv.z;
    y.w = fmaxf((v.w - g_mean[c + 3]) * g_istd[c + 3] * gamma[c + 3] + beta[c + 3], 0.0f) + xv.w;
    reinterpret_cast<float4*>(out)[idx] = y;
}

extern "C" void kernel_launch(void* const* d_in, const int* in_sizes, int n_in,
                              void* d_out, int out_size) {
    const float* x     = (const float*)d_in[0];
    const int*   ei    = (const int*)d_in[1];   // int32 edge indices
    const float* W     = (const float*)d_in[2];
    const float* b     = (const float*)d_in[3];
    const float* gamma = (const float*)d_in[4];
    const float* beta  = (const float*)d_in[5];
    float* out = (float*)d_out;

    int N = in_sizes[0] / DIM;         // 50000
    int E = in_sizes[1] / 2;           // 800000
    const int* row = ei;
    const int* col = ei + E;
    int nvec = N * (DIM / 4);
    int nb_scan = (N + SCAN_CHUNK - 1) / SCAN_CHUNK;   // 49

    k_init<<<(N + 255) / 256, 256>>>(N);
    k_degree<<<(E + 255) / 256, 256>>>(row, E);
    k_dinv<<<(N + 255) / 256, 256>>>(N);
    k_scan_sum<<<nb_scan, 256>>>(N);
    k_scan_top<<<1, 64>>>(N);
    k_scan_write<<<nb_scan, 256>>>(N);
    k_fill<<<(E + 255) / 256, 256>>>(row, col, E);
    k_gemm<<<(N + NPB - 1) / NPB, DIM>>>(x, W, N);
    k_aggregate<<<(N * 32 + 255) / 256, 256>>>(out, b, N);
    k_finstats<<<1, DIM>>>(N);
    k_final<<<(nvec + 255) / 256, 256>>>(out, x, gamma, beta, nvec);
}